// round 14
// baseline (speedup 1.0000x reference)
#include <cuda_runtime.h>
#include <cuda_bf16.h>
#include <cstdint>
#include <cstddef>

// ---------------------------------------------------------------------------
// FullAttentionEstimator: B=2, Tq=Tk=512, Q_DIM=K_DIM=1024, HID=128
//
// Factorization:
//   q = Q@Wq, k = K@Wk                       (per-row, precomputed)
//   x = [q, k, q*k]  (384)
//   LN(x)@W = r*(x@(g.W)) - r*mu*(g@W) + (b@W + bias)
//   x@(g.W) = q@W1 + k@W2 + p@W3,  p = q*k  (per pair)
// Cross term p@W3: mma.sync m16n8k16 bf16 (plain sm_80+ PTX; tcgen05 is not
// available at the bench's compute_103 target) with 3-pass bf16x3 splitting
// (p_hi@W_hi + p_hi@W_lo + p_lo@W_hi) into register fp32 accumulators.
// Tile = 64 pairs x 256 cols x K=128; 512 threads (16 warps, 8 u-cols +
// matching 8 v-cols per warp); epilogue fuses LN recombine + erf-gelu + Wo.
// ---------------------------------------------------------------------------

#define EPSV   1e-5f
#define NTILES 8192          // 2 batches * 64 i-tiles(8) * 64 j-tiles(8)

// -------------------- device scratch (no allocations allowed) --------------
__device__ float dW1[128 * 256];     // g-scaled Wu|Wv rows 0..127   [c][n]
__device__ float dW2[128 * 256];     // rows 128..255
__device__ float dG[256];            // sum_c g_c W[c][n]
__device__ float dB0[256];           // sum_c b_c W[c][n] + bias[n]
__device__ uint4 dWcT_hi[4096];      // cross weights bf16 hi, [n=256][k=128]
__device__ uint4 dWcT_lo[4096];      // cross weights bf16 lo
__device__ float d_q[1024 * 128];    // projected q rows (B*Tq)
__device__ float d_k[1024 * 128];
__device__ float dAu[1024 * 256];    // q@W1 (u|v)
__device__ float dBk[1024 * 256];    // k@W2 (u|v)
__device__ float dsq[1024], dsq2[1024], dsk[1024], dsk2[1024];

// -------------------- helpers ----------------------------------------------
__device__ __forceinline__ uint32_t smem_u32(const void* p) {
    uint32_t a;
    asm("{ .reg .u64 t; cvta.to.shared.u64 t, %1; cvt.u32.u64 %0, t; }"
        : "=r"(a) : "l"(p));
    return a;
}

__device__ __forceinline__ void ldsm4(uint32_t* r, uint32_t addr) {
    asm volatile("ldmatrix.sync.aligned.m8n8.x4.shared.b16 {%0,%1,%2,%3}, [%4];"
                 : "=r"(r[0]), "=r"(r[1]), "=r"(r[2]), "=r"(r[3]) : "r"(addr));
}
__device__ __forceinline__ void ldsm2(uint32_t* r, uint32_t addr) {
    asm volatile("ldmatrix.sync.aligned.m8n8.x2.shared.b16 {%0,%1}, [%2];"
                 : "=r"(r[0]), "=r"(r[1]) : "r"(addr));
}

__device__ __forceinline__ void hmma(float* d, const uint32_t* a,
                                     uint32_t b0, uint32_t b1) {
    asm volatile(
        "mma.sync.aligned.m16n8k16.row.col.f32.bf16.bf16.f32 "
        "{%0,%1,%2,%3}, {%4,%5,%6,%7}, {%8,%9}, {%0,%1,%2,%3};"
        : "+f"(d[0]), "+f"(d[1]), "+f"(d[2]), "+f"(d[3])
        : "r"(a[0]), "r"(a[1]), "r"(a[2]), "r"(a[3]), "r"(b0), "r"(b1));
}

__device__ __forceinline__ float gelu_ex(float v) {
    return v * (0.5f + 0.5f * erff(v * 0.70710678118654752f));
}

// ===========================================================================
// Kernel 1: derived weights. 256 blocks (col n), 384 threads (channel c).
// ===========================================================================
__global__ void deriv_kernel(const float* __restrict__ ln_g, const float* __restrict__ ln_b,
                             const float* __restrict__ Wu,   const float* __restrict__ bu,
                             const float* __restrict__ Wv,   const float* __restrict__ bv) {
    __shared__ float sg[384], sb[384];
    const int n = blockIdx.x;     // 0..255
    const int c = threadIdx.x;    // 0..383
    float w = (n < 128) ? Wu[c * 128 + n] : Wv[c * 128 + (n - 128)];
    float gw = ln_g[c] * w;
    float bw = ln_b[c] * w;
    if (c < 128)      dW1[c * 256 + n] = gw;
    else if (c < 256) dW2[(c - 128) * 256 + n] = gw;
    else {
        int k = c - 256;
        __nv_bfloat16 hi = __float2bfloat16(gw);
        __nv_bfloat16 lo = __float2bfloat16(gw - __bfloat162float(hi));
        ((__nv_bfloat16*)dWcT_hi)[n * 128 + k] = hi;
        ((__nv_bfloat16*)dWcT_lo)[n * 128 + k] = lo;
    }
    sg[c] = gw; sb[c] = bw;
    __syncthreads();
    if (c < 128) {
        sg[c] += sg[c + 128] + sg[c + 256];
        sb[c] += sb[c + 128] + sb[c + 256];
    }
    __syncthreads();
    if (c < 32) {
        float s = sg[c] + sg[c + 32] + sg[c + 64] + sg[c + 96];
        float t = sb[c] + sb[c + 32] + sb[c + 64] + sb[c + 96];
#pragma unroll
        for (int o = 16; o > 0; o >>= 1) {
            s += __shfl_xor_sync(0xffffffffu, s, o);
            t += __shfl_xor_sync(0xffffffffu, t, o);
        }
        if (c == 0) {
            dG[n] = s;
            dB0[n] = t + ((n < 128) ? bu[n] : bv[n - 128]);
        }
    }
}

// ===========================================================================
// Kernel 2: projections. 256 blocks: 0..127 -> q rows, 128..255 -> k rows.
// ===========================================================================
__global__ __launch_bounds__(128, 2)
void proj_kernel(const float* __restrict__ Q, const float* __restrict__ K,
                 const float* __restrict__ Wq, const float* __restrict__ Wk) {
    __shared__ float sh[8 * 1024];  // 32KB
    const int tid = threadIdx.x;
    const int half = blockIdx.x >> 7;
    const int r0 = (blockIdx.x & 127) * 8;
    const float* src = half ? K : Q;
    const float* W = half ? Wk : Wq;

    {
        const float4* s4 = (const float4*)(src + (size_t)r0 * 1024);
        float4* d4 = (float4*)sh;
        for (int i = tid; i < 2048; i += 128) d4[i] = s4[i];
    }
    __syncthreads();

    float acc[8];
#pragma unroll
    for (int r = 0; r < 8; r++) acc[r] = 0.f;

    for (int d = 0; d < 1024; d += 4) {
        float w0 = W[(d + 0) * 128 + tid];
        float w1 = W[(d + 1) * 128 + tid];
        float w2 = W[(d + 2) * 128 + tid];
        float w3 = W[(d + 3) * 128 + tid];
#pragma unroll
        for (int r = 0; r < 8; r++) {
            float4 qv = *(const float4*)(sh + r * 1024 + d);
            acc[r] = fmaf(qv.x, w0, acc[r]);
            acc[r] = fmaf(qv.y, w1, acc[r]);
            acc[r] = fmaf(qv.z, w2, acc[r]);
            acc[r] = fmaf(qv.w, w3, acc[r]);
        }
    }
    __syncthreads();

    float* outq = half ? d_k : d_q;
#pragma unroll
    for (int r = 0; r < 8; r++) {
        sh[r * 128 + tid] = acc[r];
        outq[(size_t)(r0 + r) * 128 + tid] = acc[r];
    }
    __syncthreads();

    if (tid < 8) {
        float s = 0.f, s2 = 0.f;
        const float* row = sh + tid * 128;
        for (int c = 0; c < 128; c++) {
            float x = row[c];
            s += x;
            s2 = fmaf(x, x, s2);
        }
        if (half) { dsk[r0 + tid] = s; dsk2[r0 + tid] = s2; }
        else      { dsq[r0 + tid] = s; dsq2[r0 + tid] = s2; }
    }

    const float* Wp = half ? dW2 : dW1;
    float au[8], av[8];
#pragma unroll
    for (int r = 0; r < 8; r++) { au[r] = 0.f; av[r] = 0.f; }
    for (int c = 0; c < 128; c++) {
        float wu = Wp[c * 256 + tid];
        float wv = Wp[c * 256 + 128 + tid];
#pragma unroll
        for (int r = 0; r < 8; r++) {
            float qv = sh[r * 128 + c];
            au[r] = fmaf(qv, wu, au[r]);
            av[r] = fmaf(qv, wv, av[r]);
        }
    }
    float* outa = half ? dBk : dAu;
#pragma unroll
    for (int r = 0; r < 8; r++) {
        outa[(size_t)(r0 + r) * 256 + tid] = au[r];
        outa[(size_t)(r0 + r) * 256 + 128 + tid] = av[r];
    }
}

// ===========================================================================
// Kernel 3: mma.sync main kernel. Persistent CTAs (1/SM), 512 threads.
// Tile = 64 pairs (8i x 8j) x N=256 (u|v) x K=128.
// Warp w (0..15): all 64 rows, u-cols [w*8, w*8+8) + v-cols [128+w*8, ...).
// ===========================================================================
// smem byte offsets
#define WHI_O   0          // 65536 : Wc^T hi bf16 [256 n-rows x 128 k] swizzled
#define WLO_O   65536      // 65536 : Wc^T lo
#define PHI_O   131072     // 16384 : P hi bf16 [64 m-rows x 128 k] swizzled
#define PLO_O   147456     // 16384 : P lo
// float offsets (region starts at byte 163840 = float 40960)
#define AU_F    40960      // 8 x 260
#define BK_F    43040      // 8 x 260
#define QS_F    45120      // 8 x 132
#define KS_F    46176      // 8 x 132
#define RED_F   47232      // 512 (8 kq-partials x 64 pairs)
#define RED2_F  47744      // 512
#define RNR_F   48256      // 128 : r[64], nr[64]
#define GG_F    48384      // 256
#define BB0_F   48640      // 256
#define WOS_F   48896      // 128
#define SCAL_F  49024      // 32 : sq[8] sq2[8] sk[8] sk2[8]
#define PD_F    49056      // 1024 : per-warp pair partials [64][16]
#define SMEM_MAIN 200320   // 50080 floats

__global__ __launch_bounds__(512, 1)
void main_kernel(const float* __restrict__ Wo, const float* __restrict__ bo,
                 float* __restrict__ out) {
    extern __shared__ char smc[];
    float* smf = (float*)smc;
    const uint32_t sbase = smem_u32(smc);
    const int tid = threadIdx.x;
    const int w = tid >> 5;            // warp 0..15
    const int lane = tid & 31;
    const int s = lane >> 3, i8 = lane & 7;
    const int tg = lane & 3, rowq = lane >> 2;

    // ---- one-time: stage Wc^T hi/lo into smem (row stride 256B, chunk^row&7)
    for (int idx = tid; idx < 4096; idx += 512) {
        const int n = idx >> 4, c = idx & 15;
        const int off = n * 256 + ((c ^ (n & 7)) << 4);
        *(uint4*)(smc + WHI_O + off) = dWcT_hi[idx];
        *(uint4*)(smc + WLO_O + off) = dWcT_lo[idx];
    }
    if (tid < 256) {
        smf[GG_F + tid] = dG[tid];
        smf[BB0_F + tid] = dB0[tid];
        if (tid < 128) smf[WOS_F + tid] = Wo[tid];
    }
    __syncthreads();

    // ---- hoist loop-invariant epilogue operands (thread's fixed h pair) ----
    const int h0 = w * 8 + tg * 2;
    const float2 gu2  = *(const float2*)(smf + GG_F + h0);
    const float2 gv2  = *(const float2*)(smf + GG_F + 128 + h0);
    const float2 b0u2 = *(const float2*)(smf + BB0_F + h0);
    const float2 b0v2 = *(const float2*)(smf + BB0_F + 128 + h0);
    const float2 wo2  = *(const float2*)(smf + WOS_F + h0);
    const float bo_v = bo[0];
    const int grid = gridDim.x;

    // ldmatrix lane-address components (constant per thread)
    const uint32_t a_base  = sbase + PHI_O + ((((s & 1) << 3) + i8) << 8);
    const uint32_t bu_base = sbase + WHI_O + (uint32_t)((w * 8 + i8) << 8);
    const uint32_t bv_base = bu_base + 32768;   // +128 n-rows
    const int kb_a = (s >> 1), kb_b = (s & 1);

    for (int t = blockIdx.x; t < NTILES; t += grid) {
        const int b = t >> 12;
        const int i0 = ((t >> 6) & 63) * 8;
        const int j0 = (t & 63) * 8;

        // ---- per-tile operand loads gmem -> smem ----
        {
            const float4* ag = (const float4*)(dAu + (size_t)(b * 512 + i0) * 256);
            *(float4*)(smf + AU_F + (tid >> 6) * 260 + (tid & 63) * 4) = ag[tid];
            const float4* bg = (const float4*)(dBk + (size_t)(b * 512 + j0) * 256);
            *(float4*)(smf + BK_F + (tid >> 6) * 260 + (tid & 63) * 4) = bg[tid];
            if (tid < 256) {
                const float4* qg = (const float4*)(d_q + (size_t)(b * 512 + i0) * 128);
                *(float4*)(smf + QS_F + (tid >> 5) * 132 + (tid & 31) * 4) = qg[tid];
            } else {
                const int t2 = tid - 256;
                const float4* kg = (const float4*)(d_k + (size_t)(b * 512 + j0) * 128);
                *(float4*)(smf + KS_F + (t2 >> 5) * 132 + (t2 & 31) * 4) = kg[t2];
            }
            if (tid < 8)       smf[SCAL_F + tid] = dsq [b * 512 + i0 + tid];
            else if (tid < 16) smf[SCAL_F + tid] = dsq2[b * 512 + i0 + tid - 8];
            else if (tid < 24) smf[SCAL_F + tid] = dsk [b * 512 + j0 + tid - 16];
            else if (tid < 32) smf[SCAL_F + tid] = dsk2[b * 512 + j0 + tid - 24];
        }
        __syncthreads();  // B1: operands visible

        // ---- build P hi+lo (bf16, swizzled) + exact fp32 stats partials ----
        {
            const int m = tid & 63, kq = tid >> 6;       // kq 0..7 -> 16 k each
            const int iB = m >> 3, jB = m & 7;
            const float* qrow = smf + QS_F + iB * 132;
            const float* krow = smf + KS_F + jB * 132;
            float ss = 0.f, s2 = 0.f;
#pragma unroll
            for (int c8 = 0; c8 < 2; c8++) {
                const int kk = kq * 16 + c8 * 8;
                float4 qa = *(const float4*)(qrow + kk);
                float4 qb = *(const float4*)(qrow + kk + 4);
                float4 ka = *(const float4*)(krow + kk);
                float4 kb = *(const float4*)(krow + kk + 4);
                float p0 = qa.x * ka.x, p1 = qa.y * ka.y;
                float p2 = qa.z * ka.z, p3 = qa.w * ka.w;
                float p4 = qb.x * kb.x, p5 = qb.y * kb.y;
                float p6 = qb.z * kb.z, p7 = qb.w * kb.w;
                ss += ((p0 + p1) + (p2 + p3)) + ((p4 + p5) + (p6 + p7));
                s2 = fmaf(p0, p0, s2); s2 = fmaf(p1, p1, s2);
                s2 = fmaf(p2, p2, s2); s2 = fmaf(p3, p3, s2);
                s2 = fmaf(p4, p4, s2); s2 = fmaf(p5, p5, s2);
                s2 = fmaf(p6, p6, s2); s2 = fmaf(p7, p7, s2);
                __nv_bfloat162 h0x = __floats2bfloat162_rn(p0, p1);
                __nv_bfloat162 h1x = __floats2bfloat162_rn(p2, p3);
                __nv_bfloat162 h2x = __floats2bfloat162_rn(p4, p5);
                __nv_bfloat162 h3x = __floats2bfloat162_rn(p6, p7);
                __nv_bfloat162 l0 = __floats2bfloat162_rn(p0 - __low2float(h0x), p1 - __high2float(h0x));
                __nv_bfloat162 l1 = __floats2bfloat162_rn(p2 - __low2float(h1x), p3 - __high2float(h1x));
                __nv_bfloat162 l2 = __floats2bfloat162_rn(p4 - __low2float(h2x), p5 - __high2float(h2x));
                __nv_bfloat162 l3 = __floats2bfloat162_rn(p6 - __low2float(h3x), p7 - __high2float(h3x));
                uint4 sh, sl;
                sh.x = *(uint32_t*)&h0x; sh.y = *(uint32_t*)&h1x;
                sh.z = *(uint32_t*)&h2x; sh.w = *(uint32_t*)&h3x;
                sl.x = *(uint32_t*)&l0; sl.y = *(uint32_t*)&l1;
                sl.z = *(uint32_t*)&l2; sl.w = *(uint32_t*)&l3;
                const int off = m * 256 + (((kk >> 3) ^ (m & 7)) << 4);
                *(uint4*)(smc + PHI_O + off) = sh;
                *(uint4*)(smc + PLO_O + off) = sl;
            }
            smf[RED_F + kq * 64 + m] = ss;
            smf[RED2_F + kq * 64 + m] = s2;
        }
        __syncthreads();  // B2: P + stats partials visible

        // ---- LN stats (tid<64) then everyone runs the MMA loop ----
        if (tid < 64) {
            float ss = 0.f, s2 = 0.f;
#pragma unroll
            for (int o = 0; o < 8; o++) {
                ss += smf[RED_F + o * 64 + tid];
                s2 += smf[RED2_F + o * 64 + tid];
            }
            const int i2 = tid >> 3, j2 = tid & 7;
            float mu = (smf[SCAL_F + i2] + smf[SCAL_F + 16 + j2] + ss) * (1.f / 384.f);
            float e2 = (smf[SCAL_F + 8 + i2] + smf[SCAL_F + 24 + j2] + s2) * (1.f / 384.f);
            float r = rsqrtf(e2 - mu * mu + EPSV);
            smf[RNR_F + tid] = r;
            smf[RNR_F + 64 + tid] = -r * mu;
        }

        // ---- cross GEMM: 3-pass bf16x3 via mma.sync ----
        float D[32];
#pragma unroll
        for (int x = 0; x < 32; x++) D[x] = 0.f;

#pragma unroll 2
        for (int kf = 0; kf < 8; kf++) {
            uint32_t bu[2], blu[2], bv[2], blv[2];
            const uint32_t cb = (uint32_t)(((2 * kf + kb_b) ^ i8) << 4);
            ldsm2(bu,  bu_base + cb);
            ldsm2(blu, bu_base + 65536 + cb);
            ldsm2(bv,  bv_base + cb);
            ldsm2(blv, bv_base + 65536 + cb);
            const uint32_t ca = (uint32_t)(((2 * kf + kb_a) ^ i8) << 4);
#pragma unroll
            for (int mf = 0; mf < 4; mf++) {
                uint32_t ah[4], al[4];
                const uint32_t aaddr = a_base + mf * 4096 + ca;
                ldsm4(ah, aaddr);
                ldsm4(al, aaddr + 16384);
                hmma(D + mf * 8 + 0, ah, bu[0],  bu[1]);
                hmma(D + mf * 8 + 0, al, bu[0],  bu[1]);
                hmma(D + mf * 8 + 0, ah, blu[0], blu[1]);
                hmma(D + mf * 8 + 4, ah, bv[0],  bv[1]);
                hmma(D + mf * 8 + 4, al, bv[0],  bv[1]);
                hmma(D + mf * 8 + 4, ah, blv[0], blv[1]);
            }
        }
        __syncthreads();  // B3: D complete; RNR published

        // ---- fused epilogue on register accumulators ----
#pragma unroll
        for (int mf = 0; mf < 4; mf++) {
#pragma unroll
            for (int hf = 0; hf < 2; hf++) {
                const int p = mf * 16 + hf * 8 + rowq;
                const float rr = smf[RNR_F + p];
                const float nr = smf[RNR_F + 64 + p];
                const int ip = p >> 3, jp = p & 7;
                const float2 au2 = *(const float2*)(smf + AU_F + ip * 260 + h0);
                const float2 av2 = *(const float2*)(smf + AU_F + ip * 260 + 128 + h0);
                const float2 bk2 = *(const float2*)(smf + BK_F + jp * 260 + h0);
                const float2 bv2p = *(const float2*)(smf + BK_F + jp * 260 + 128 + h0);
                const float Cu0 = D[mf * 8 + hf * 2 + 0];
                const float Cu1 = D[mf * 8 + hf * 2 + 1];
                const float Cv0 = D[mf * 8 + 4 + hf * 2 + 0];
                const float Cv1 = D[mf * 8 + 4 + hf * 2 + 1];
                float u0 = fmaf(rr, au2.x + bk2.x + Cu0, fmaf(nr, gu2.x, b0u2.x));
                float v0 = fmaf(rr, av2.x + bv2p.x + Cv0, fmaf(nr, gv2.x, b0v2.x));
                float u1 = fmaf(rr, au2.y + bk2.y + Cu1, fmaf(nr, gu2.y, b0u2.y));
                float v1 = fmaf(rr, av2.y + bv2p.y + Cv1, fmaf(nr, gv2.y, b0v2.y));
                float z = fmaf(u0 * gelu_ex(v0), wo2.x, u1 * gelu_ex(v1) * wo2.y);
                z += __shfl_xor_sync(0xffffffffu, z, 1);
                z += __shfl_xor_sync(0xffffffffu, z, 2);
                if (tg == 0) smf[PD_F + p * 16 + w] = z;
            }
        }
        __syncthreads();  // B4: PD visible; epilogue smem reads retired

        // ---- combine 16 warp partials, store ----
        if (tid < 64) {
            float acc = bo_v;
#pragma unroll
            for (int ww = 0; ww < 16; ww++) acc += smf[PD_F + tid * 16 + ww];
            out[(size_t)(b * 512 + i0 + (tid >> 3)) * 512 + j0 + (tid & 7)] = acc;
        }
        // no top-of-loop barrier needed: B4 already separates this tile's
        // epilogue smem reads from next tile's loads (disjoint from PD).
    }
}

// ===========================================================================
// launcher
// ===========================================================================
extern "C" void kernel_launch(void* const* d_in, const int* in_sizes, int n_in,
                              void* d_out, int out_size) {
    const float* Q    = (const float*)d_in[0];
    const float* K    = (const float*)d_in[1];
    const float* Wq   = (const float*)d_in[2];
    const float* Wk   = (const float*)d_in[3];
    const float* ln_g = (const float*)d_in[4];
    const float* ln_b = (const float*)d_in[5];
    const float* Wu   = (const float*)d_in[6];
    const float* bu   = (const float*)d_in[7];
    const float* Wv   = (const float*)d_in[8];
    const float* bv   = (const float*)d_in[9];
    const float* Wo   = (const float*)d_in[10];
    const float* bo   = (const float*)d_in[11];
    float* out = (float*)d_out;

    int nsm = 148;
    cudaDeviceGetAttribute(&nsm, cudaDevAttrMultiProcessorCount, 0);

    cudaFuncSetAttribute(main_kernel, cudaFuncAttributeMaxDynamicSharedMemorySize, SMEM_MAIN);

    deriv_kernel<<<256, 384>>>(ln_g, ln_b, Wu, bu, Wv, bv);
    proj_kernel<<<256, 128>>>(Q, K, Wq, Wk);
    main_kernel<<<nsm, 512, SMEM_MAIN>>>(Wo, bo, out);
}